// round 14
// baseline (speedup 1.0000x reference)
#include <cuda_runtime.h>
#include <cuda_fp16.h>
#include <math.h>
#include <stdint.h>

#define NMAX 50000
#define EMAX 600000
#define HID  128
#define NG   64
#define FULLMASK 0xffffffffu

#define PADH 136                               // halves per smem row
#define GEMM_SMEM (128 * PADH * 2 * 2)         // sWt + sA, fp16
#define GEMM_GRID 296                          // 148 SMs x 2 CTAs

// ---------------- device scratch ----------------
__device__ __align__(16) __half g_hh [(size_t)NMAX * HID];  // fp16 agg output (GEMM input)
__device__ __align__(16) __half g_xph[(size_t)NMAX * HID];  // fp16 gather payload (h_l)
__device__ float g_als[NMAX];
__device__ float g_ald[NMAX];
__device__ __align__(16) float g_pool[NG * HID + NG];       // pool + cnt (zeroed by k_final)
__device__ __align__(16) float g_cs[512];                   // cs2, cd2, cs3, cd3
__device__ int   g_deg[NMAX];                               // zeroed by k_scan
__device__ int   g_rowptr[NMAX + 1];
__device__ int   g_wptr[NMAX];
__device__ int   g_csrc[EMAX];
__device__ int   g_bsum[64];
__device__ unsigned long long g_brdy;                       // lookback ready-mask (self-reset)
__device__ int   g_done;                                    // completion counter (self-reset)

__device__ __forceinline__ float lrelu(float a) { return (a > 0.f) ? a : 0.2f * a; }

__device__ __forceinline__ void mma_f16(float c[4], const uint32_t a[4],
                                        uint32_t b0, uint32_t b1) {
    asm volatile(
        "mma.sync.aligned.m16n8k16.row.col.f32.f16.f16.f32 "
        "{%0,%1,%2,%3}, {%4,%5,%6,%7}, {%8,%9}, {%0,%1,%2,%3};"
        : "+f"(c[0]), "+f"(c[1]), "+f"(c[2]), "+f"(c[3])
        : "r"(a[0]), "r"(a[1]), "r"(a[2]), "r"(a[3]), "r"(b0), "r"(b1));
}

__device__ __forceinline__ float4 h4_to_f4(uint2 u) {
    float2 a = __half22float2(*(__half2*)&u.x);
    float2 b = __half22float2(*(__half2*)&u.y);
    return make_float4(a.x, a.y, b.x, b.y);
}

// ================= CSR build (stream s2) =================
// 2 edges per thread (int2 loads)
__global__ void k_hist(const int* __restrict__ ei, int E) {
    int p = blockIdx.x * blockDim.x + threadIdx.x;
    int e = p * 2;
    if (e + 1 < E) {
        int2 d2 = *(const int2*)&ei[E + e];
        atomicAdd(&g_deg[d2.x], 1);
        atomicAdd(&g_deg[d2.y], 1);
    } else if (e < E) {
        atomicAdd(&g_deg[ei[E + e]], 1);
    }
}

// single-pass decoupled-lookback exclusive scan; also re-zeroes g_deg
__global__ void k_scan(int n, int nb) {
    __shared__ int warp_sums[32];
    __shared__ int s_off;
    int tid = threadIdx.x, lane = tid & 31, wid = tid >> 5;
    int b = blockIdx.x;
    int i = b * 1024 + tid;
    int v = (i < n) ? g_deg[i] : 0;
    if (i < n) g_deg[i] = 0;          // restore zero-invariant
    int x = v;
#pragma unroll
    for (int o = 1; o < 32; o <<= 1) {
        int y = __shfl_up_sync(FULLMASK, x, o);
        if (lane >= o) x += y;
    }
    if (lane == 31) warp_sums[wid] = x;
    __syncthreads();
    if (wid == 0) {
        int w = warp_sums[lane];
#pragma unroll
        for (int o = 1; o < 32; o <<= 1) {
            int y = __shfl_up_sync(FULLMASK, w, o);
            if (lane >= o) w += y;
        }
        warp_sums[lane] = w;
    }
    __syncthreads();

    if (tid == 0) {
        int tot = warp_sums[31];
        g_bsum[b] = tot;
        __threadfence();
        atomicOr(&g_brdy, 1ull << b);
        unsigned long long need = (b == 0) ? 0ull : ((1ull << b) - 1ull);
        if (need) {
            while ((atomicOr(&g_brdy, 0ull) & need) != need) { }
        }
        int off = 0;
        for (int j = 0; j < b; j++) off += g_bsum[j];
        s_off = off;
        if (b == nb - 1) g_rowptr[n] = off + tot;
        __threadfence();
        int d = atomicAdd(&g_done, 1);
        if (d == nb - 1) {            // last finisher resets for next replay
            g_brdy = 0ull;
            g_done = 0;
            __threadfence();
        }
    }
    __syncthreads();
    int excl = s_off + (wid ? warp_sums[wid - 1] : 0) + x - v;
    if (i < n) { g_rowptr[i] = excl; g_wptr[i] = excl; }
}

// 2 edges per thread (int2 loads)
__global__ void k_scatter(const int* __restrict__ ei, int E) {
    int p = blockIdx.x * blockDim.x + threadIdx.x;
    int e = p * 2;
    if (e + 1 < E) {
        int2 s2 = *(const int2*)&ei[e];
        int2 d2 = *(const int2*)&ei[E + e];
        int p0 = atomicAdd(&g_wptr[d2.x], 1);
        g_csrc[p0] = s2.x;
        int p1 = atomicAdd(&g_wptr[d2.y], 1);
        g_csrc[p1] = s2.y;
    } else if (e < E) {
        int d = ei[E + e];
        int pos = atomicAdd(&g_wptr[d], 1);
        g_csrc[pos] = ei[e];
    }
}

// ================= prep: cs_l = W_l @ a_src_l, cd_l = W_l @ a_dst_l (l=2,3) =========
__global__ void k_prep(const float* __restrict__ W2, const float* __restrict__ as2,
                       const float* __restrict__ ad2,
                       const float* __restrict__ W3, const float* __restrict__ as3,
                       const float* __restrict__ ad3) {
    int t = threadIdx.x;   // 256
    const float* W  = (t < 128) ? W2 : W3;
    const float* av = (t < 128) ? as2 : as3;
    const float* dv = (t < 128) ? ad2 : ad3;
    int r = t & 127;
    float s = 0.f, d = 0.f;
    for (int j = 0; j < 128; j++) {
        float w = W[r * 128 + j];
        s += w * av[j];
        d += w * dv[j];
    }
    int base = (t < 128) ? 0 : 256;
    g_cs[base + r]       = s;
    g_cs[base + 128 + r] = d;
}

// ================= layer 1: scalar agg (CSR) + expand + layer-2 attn scalars ========
__global__ __launch_bounds__(256) void k_l1agg(const float* __restrict__ x,
                                               const float* __restrict__ W1,
                                               const float* __restrict__ as1,
                                               const float* __restrict__ ad1,
                                               const float* __restrict__ b1, int n) {
    __shared__ float sc0, sc1;
    __shared__ float partS[4], partD[4];
    int tid = threadIdx.x;
    {
        float s = 0.f, d = 0.f;
        if (tid < 128) {
            float w = W1[tid];
            s = w * as1[tid];
            d = w * ad1[tid];
        }
#pragma unroll
        for (int o = 16; o > 0; o >>= 1) {
            s += __shfl_down_sync(FULLMASK, s, o);
            d += __shfl_down_sync(FULLMASK, d, o);
        }
        if (tid < 128 && (tid & 31) == 0) { partS[tid >> 5] = s; partD[tid >> 5] = d; }
        __syncthreads();
        if (tid == 0) sc0 = partS[0] + partS[1] + partS[2] + partS[3];
        if (tid == 1) sc1 = partD[0] + partD[1] + partD[2] + partD[3];
        __syncthreads();
    }
    int w = (blockIdx.x * blockDim.x + tid) >> 5;
    int lane = tid & 31;
    if (w >= n) return;
    float c0 = sc0, c1 = sc1;
    float xd = x[w];
    float ald_d = xd * c1;
    float a_self = lrelu(xd * c0 + ald_d);
    int row = g_rowptr[w], end = g_rowptr[w + 1];
    int cnt = end - row;
    float a1;

    if (cnt <= 32) {
        float xv = 0.f, a_reg = -1e30f;
        if (lane < cnt) {
            int s = g_csrc[row + lane];
            xv = x[s];
            a_reg = lrelu(xv * c0 + ald_d);
        }
        float m = fmaxf(a_reg, a_self);
#pragma unroll
        for (int o = 16; o > 0; o >>= 1)
            m = fmaxf(m, __shfl_xor_sync(FULLMASK, m, o));
        float p = (lane < cnt) ? __expf(a_reg - m) : 0.f;
        float num = p * xv, den = p;
#pragma unroll
        for (int o = 16; o > 0; o >>= 1) {
            num += __shfl_xor_sync(FULLMASK, num, o);
            den += __shfl_xor_sync(FULLMASK, den, o);
        }
        float eself = __expf(a_self - m);
        a1 = (num + eself * xd) / (den + eself);
    } else {
        float m = a_self;
        for (int e = row + lane; e < end; e += 32)
            m = fmaxf(m, lrelu(__ldg(&x[g_csrc[e]]) * c0 + ald_d));
#pragma unroll
        for (int o = 16; o > 0; o >>= 1)
            m = fmaxf(m, __shfl_xor_sync(FULLMASK, m, o));
        float num = 0.f, den = 0.f;
        for (int e = row + lane; e < end; e += 32) {
            float xv = __ldg(&x[g_csrc[e]]);
            float p = __expf(lrelu(xv * c0 + ald_d) - m);
            num += p * xv; den += p;
        }
#pragma unroll
        for (int o = 16; o > 0; o >>= 1) {
            num += __shfl_xor_sync(FULLMASK, num, o);
            den += __shfl_xor_sync(FULLMASK, den, o);
        }
        float eself = __expf(a_self - m);
        a1 = (num + eself * xd) / (den + eself);
    }

    float4 w4 = ((const float4*)W1)[lane];
    float4 b4 = ((const float4*)b1)[lane];
    float4 v;
    v.x = fmaxf(a1 * w4.x + b4.x, 0.f);
    v.y = fmaxf(a1 * w4.y + b4.y, 0.f);
    v.z = fmaxf(a1 * w4.z + b4.z, 0.f);
    v.w = fmaxf(a1 * w4.w + b4.w, 0.f);
    uint2 st;
    *(__half2*)&st.x = __floats2half2_rn(v.x, v.y);
    *(__half2*)&st.y = __floats2half2_rn(v.z, v.w);
    ((uint2*)g_xph)[(size_t)w * 32 + lane] = st;
    float4 cs4 = ((const float4*)g_cs)[lane];
    float4 cd4 = ((const float4*)(g_cs + 128))[lane];
    float ds = v.x * cs4.x + v.y * cs4.y + v.z * cs4.z + v.w * cs4.w;
    float dd = v.x * cd4.x + v.y * cd4.y + v.z * cd4.z + v.w * cd4.w;
#pragma unroll
    for (int o = 16; o > 0; o >>= 1) {
        ds += __shfl_down_sync(FULLMASK, ds, o);
        dd += __shfl_down_sync(FULLMASK, dd, o);
    }
    if (lane == 0) { g_als[w] = ds; g_ald[w] = dd; }
}

// ============ wide GAT softmax-aggregate (warp per dst node) -> fp16 g_hh ===========
__global__ __launch_bounds__(256) void k_gat_agg(int n) {
    int w = (blockIdx.x * blockDim.x + threadIdx.x) >> 5;
    int lane = threadIdx.x & 31;
    if (w >= n) return;
    int row = g_rowptr[w], end = g_rowptr[w + 1];
    int cnt = end - row;
    float ald_d = g_ald[w];
    float a_self = lrelu(g_als[w] + ald_d);
    const uint2* xpv = (const uint2*)g_xph;
    float4 acc;

    if (cnt <= 32) {
        int s_reg = 0;
        float a_reg = -1e30f;
        if (lane < cnt) {
            s_reg = g_csrc[row + lane];
            a_reg = lrelu(g_als[s_reg] + ald_d);
        }
        float m = fmaxf(a_reg, a_self);
#pragma unroll
        for (int o = 16; o > 0; o >>= 1)
            m = fmaxf(m, __shfl_xor_sync(FULLMASK, m, o));
        float p = (lane < cnt) ? __expf(a_reg - m) : 0.f;
        float den = p;
#pragma unroll
        for (int o = 16; o > 0; o >>= 1)
            den += __shfl_xor_sync(FULLMASK, den, o);
        float eself = __expf(a_self - m);
        float rden = 1.0f / (den + eself);
        p *= rden;

        float cself = eself * rden;
        float4 sv = h4_to_f4(xpv[(size_t)w * 32 + lane]);
        acc = make_float4(cself * sv.x, cself * sv.y, cself * sv.z, cself * sv.w);
        int j = 0;
        for (; j + 4 <= cnt; j += 4) {
            float c0 = __shfl_sync(FULLMASK, p, j + 0);
            float c1 = __shfl_sync(FULLMASK, p, j + 1);
            float c2 = __shfl_sync(FULLMASK, p, j + 2);
            float c3 = __shfl_sync(FULLMASK, p, j + 3);
            int s0 = __shfl_sync(FULLMASK, s_reg, j + 0);
            int s1 = __shfl_sync(FULLMASK, s_reg, j + 1);
            int s2 = __shfl_sync(FULLMASK, s_reg, j + 2);
            int s3 = __shfl_sync(FULLMASK, s_reg, j + 3);
            uint2 u0 = xpv[(size_t)s0 * 32 + lane];
            uint2 u1 = xpv[(size_t)s1 * 32 + lane];
            uint2 u2 = xpv[(size_t)s2 * 32 + lane];
            uint2 u3 = xpv[(size_t)s3 * 32 + lane];
            float4 v0 = h4_to_f4(u0), v1 = h4_to_f4(u1);
            float4 v2 = h4_to_f4(u2), v3 = h4_to_f4(u3);
            acc.x += c0 * v0.x + c1 * v1.x + c2 * v2.x + c3 * v3.x;
            acc.y += c0 * v0.y + c1 * v1.y + c2 * v2.y + c3 * v3.y;
            acc.z += c0 * v0.z + c1 * v1.z + c2 * v2.z + c3 * v3.z;
            acc.w += c0 * v0.w + c1 * v1.w + c2 * v2.w + c3 * v3.w;
        }
        for (; j < cnt; j++) {
            float coef = __shfl_sync(FULLMASK, p, j);
            int s = __shfl_sync(FULLMASK, s_reg, j);
            float4 v = h4_to_f4(xpv[(size_t)s * 32 + lane]);
            acc.x += coef * v.x; acc.y += coef * v.y;
            acc.z += coef * v.z; acc.w += coef * v.w;
        }
    } else {
        float m = a_self;
        for (int e = row + lane; e < end; e += 32)
            m = fmaxf(m, lrelu(__ldg(&g_als[g_csrc[e]]) + ald_d));
#pragma unroll
        for (int o = 16; o > 0; o >>= 1)
            m = fmaxf(m, __shfl_xor_sync(FULLMASK, m, o));
        float den = (lane == 0) ? __expf(a_self - m) : 0.f;
        for (int e = row + lane; e < end; e += 32)
            den += __expf(lrelu(__ldg(&g_als[g_csrc[e]]) + ald_d) - m);
#pragma unroll
        for (int o = 16; o > 0; o >>= 1)
            den += __shfl_xor_sync(FULLMASK, den, o);
        float rden = 1.0f / den;
        float cself = __expf(a_self - m) * rden;
        float4 sv = h4_to_f4(xpv[(size_t)w * 32 + lane]);
        acc = make_float4(cself * sv.x, cself * sv.y, cself * sv.z, cself * sv.w);
        for (int j = row; j < end; j++) {
            int s = g_csrc[j];
            float coef = __expf(lrelu(g_als[s] + ald_d) - m) * rden;
            float4 v = h4_to_f4(xpv[(size_t)s * 32 + lane]);
            acc.x += coef * v.x; acc.y += coef * v.y;
            acc.z += coef * v.z; acc.w += coef * v.w;
        }
    }
    uint2 st;
    *(__half2*)&st.x = __floats2half2_rn(acc.x, acc.y);
    *(__half2*)&st.y = __floats2half2_rn(acc.z, acc.w);
    ((uint2*)g_hh)[(size_t)w * 32 + lane] = st;
}

// ============ fp16 HMMA GEMM (persistent, grid-stride over 128-row tiles) ===========
// FINAL=0: write fp16 payload + next als/ald.  FINAL=1: pool by batch.
template <int FINAL>
__global__ __launch_bounds__(256, 2) void k_gemm_tc(const float* __restrict__ W,
                                                    const float* __restrict__ bias,
                                                    const float* __restrict__ csv,
                                                    const float* __restrict__ cdv,
                                                    const int* __restrict__ batch, int n) {
    extern __shared__ __half smem_h[];
    __half* sWt = smem_h;                  // [128 n][PADH k] transposed fp16
    __half* sA  = smem_h + 128 * PADH;     // [128 row][PADH k] fp16
    __shared__ float sS[128], sD[128];

    const int tid = threadIdx.x;
    const int wid = tid >> 5, lane = tid & 31;
    const int wr = wid & 3;
    const int wc = wid >> 2;
    const int gid = lane >> 2, tig = lane & 3;

    // stage W transposed to fp16 once: sWt[n][k] = W[k][n]
    for (int i = tid; i < 4096; i += 256) {
        int nn = i & 127;
        int k4 = i >> 7;
        float w0 = W[(k4 * 4 + 0) * 128 + nn];
        float w1 = W[(k4 * 4 + 1) * 128 + nn];
        float w2 = W[(k4 * 4 + 2) * 128 + nn];
        float w3 = W[(k4 * 4 + 3) * 128 + nn];
        __half2* dst = (__half2*)&sWt[nn * PADH + k4 * 4];
        dst[0] = __floats2half2_rn(w0, w1);
        dst[1] = __floats2half2_rn(w2, w3);
    }

    for (int row0 = blockIdx.x * 128; row0 < n; row0 += gridDim.x * 128) {
        __syncthreads();   // sA/sS/sD safe to overwrite (W staging covered on first pass)
        if (FINAL == 0 && tid < 128) { sS[tid] = 0.f; sD[tid] = 0.f; }

        // stage A (straight fp16 copy, 16B chunks)
        {
            const uint4* src = (const uint4*)g_hh;
            for (int idx = tid; idx < 2048; idx += 256) {
                int r = idx >> 4;
                int c = idx & 15;
                uint4 v = make_uint4(0u, 0u, 0u, 0u);
                if (row0 + r < n) v = src[(size_t)(row0 + r) * 16 + c];
                *(uint4*)&sA[r * PADH + c * 8] = v;
            }
        }
        __syncthreads();

        float acc[2][8][4];
#pragma unroll
        for (int mt = 0; mt < 2; mt++)
#pragma unroll
            for (int j = 0; j < 8; j++)
#pragma unroll
                for (int q = 0; q < 4; q++) acc[mt][j][q] = 0.f;

#pragma unroll
        for (int ks = 0; ks < 8; ks++) {
            int k0 = ks * 16;
            uint32_t a[2][4];
#pragma unroll
            for (int mt = 0; mt < 2; mt++) {
                int base = wr * 32 + mt * 16;
                a[mt][0] = *(uint32_t*)&sA[(base + gid)     * PADH + k0 + tig * 2];
                a[mt][1] = *(uint32_t*)&sA[(base + gid + 8) * PADH + k0 + tig * 2];
                a[mt][2] = *(uint32_t*)&sA[(base + gid)     * PADH + k0 + tig * 2 + 8];
                a[mt][3] = *(uint32_t*)&sA[(base + gid + 8) * PADH + k0 + tig * 2 + 8];
            }
#pragma unroll
            for (int j = 0; j < 8; j++) {
                int col = wc * 64 + j * 8 + gid;
                uint32_t b0 = *(uint32_t*)&sWt[col * PADH + k0 + tig * 2];
                uint32_t b1 = *(uint32_t*)&sWt[col * PADH + k0 + tig * 2 + 8];
                mma_f16(acc[0][j], a[0], b0, b1);
                mma_f16(acc[1][j], a[1], b0, b1);
            }
        }
        __syncthreads();

#pragma unroll
        for (int mt = 0; mt < 2; mt++) {
            int lr0 = wr * 32 + mt * 16 + gid;
            int lr1 = lr0 + 8;
            int r0 = row0 + lr0, r1 = row0 + lr1;
            int gg0 = 0, gg1 = 0;
            if (FINAL == 1) {
                gg0 = (r0 < n) ? batch[r0] : 0;
                gg1 = (r1 < n) ? batch[r1] : 0;
            }
            float ps0 = 0.f, pd0 = 0.f, ps1 = 0.f, pd1 = 0.f;
#pragma unroll
            for (int j = 0; j < 8; j++) {
                int col = wc * 64 + j * 8 + tig * 2;
                float bb0 = __ldg(&bias[col]), bb1 = __ldg(&bias[col + 1]);
                float v00 = fmaxf(acc[mt][j][0] + bb0, 0.f);
                float v01 = fmaxf(acc[mt][j][1] + bb1, 0.f);
                float v10 = fmaxf(acc[mt][j][2] + bb0, 0.f);
                float v11 = fmaxf(acc[mt][j][3] + bb1, 0.f);
                if (FINAL == 0) {
                    float av0 = __ldg(&csv[col]), av1 = __ldg(&csv[col + 1]);
                    float dv0 = __ldg(&cdv[col]), dv1 = __ldg(&cdv[col + 1]);
                    if (r0 < n)
                        *(__half2*)&g_xph[(size_t)r0 * 128 + col] = __floats2half2_rn(v00, v01);
                    if (r1 < n)
                        *(__half2*)&g_xph[(size_t)r1 * 128 + col] = __floats2half2_rn(v10, v11);
                    ps0 += v00 * av0 + v01 * av1;
                    pd0 += v00 * dv0 + v01 * dv1;
                    ps1 += v10 * av0 + v11 * av1;
                    pd1 += v10 * dv0 + v11 * dv1;
                } else {
                    float n00 = __shfl_xor_sync(FULLMASK, v00, 1);
                    float n01 = __shfl_xor_sync(FULLMASK, v01, 1);
                    float n10 = __shfl_xor_sync(FULLMASK, v10, 1);
                    float n11 = __shfl_xor_sync(FULLMASK, v11, 1);
                    if ((tig & 1) == 0) {
                        int cb = wc * 64 + j * 8 + tig * 2;
                        if (r0 < n)
                            atomicAdd((float4*)&g_pool[gg0 * 128 + cb],
                                      make_float4(v00, v01, n00, n01));
                        if (r1 < n)
                            atomicAdd((float4*)&g_pool[gg1 * 128 + cb],
                                      make_float4(v10, v11, n10, n11));
                    }
                }
            }
            if (FINAL == 0) {
                atomicAdd(&sS[lr0], ps0); atomicAdd(&sD[lr0], pd0);
                atomicAdd(&sS[lr1], ps1); atomicAdd(&sD[lr1], pd1);
            } else if (wc == 0 && tig == 0) {
                if (r0 < n) atomicAdd(&g_pool[NG * HID + gg0], 1.0f);
                if (r1 < n) atomicAdd(&g_pool[NG * HID + gg1], 1.0f);
            }
        }
        if (FINAL == 0) {
            __syncthreads();
            if (tid < 128 && row0 + tid < n) {
                g_als[row0 + tid] = sS[tid];
                g_ald[row0 + tid] = sD[tid];
            }
        }
    }
}

// ================= head (re-zeroes g_pool for next replay) =================
__global__ void k_final(const float* __restrict__ Wlin, const float* __restrict__ blin,
                        float* __restrict__ out) {
    int g = blockIdx.x;
    int j = threadIdx.x;
    __shared__ float s0[128], s1[128];
    float cnt = fmaxf(g_pool[NG * HID + g], 1.0f);
    float p = g_pool[g * 128 + j] / cnt;
    s0[j] = p * Wlin[j * 2 + 0];
    s1[j] = p * Wlin[j * 2 + 1];
    __syncthreads();
    g_pool[g * 128 + j] = 0.f;
    if (j == 0) g_pool[NG * HID + g] = 0.f;
#pragma unroll
    for (int st = 64; st > 0; st >>= 1) {
        if (j < st) { s0[j] += s0[j + st]; s1[j] += s1[j + st]; }
        __syncthreads();
    }
    if (j == 0) {
        out[g * 2 + 0] = 1.0f / (1.0f + __expf(-(s0[0] + blin[0])));
        out[g * 2 + 1] = 1.0f / (1.0f + __expf(-(s1[0] + blin[1])));
    }
}

// ================= host =================
extern "C" void kernel_launch(void* const* d_in, const int* in_sizes, int n_in,
                              void* d_out, int out_size) {
    const float* x     = (const float*)d_in[0];
    const int*   ei    = (const int*)d_in[1];
    const int*   batch = (const int*)d_in[2];
    const float* Wl[3] = { (const float*)d_in[3], (const float*)d_in[7],  (const float*)d_in[11] };
    const float* As[3] = { (const float*)d_in[4], (const float*)d_in[8],  (const float*)d_in[12] };
    const float* Ad[3] = { (const float*)d_in[5], (const float*)d_in[9],  (const float*)d_in[13] };
    const float* Bs[3] = { (const float*)d_in[6], (const float*)d_in[10], (const float*)d_in[14] };
    const float* Wlin  = (const float*)d_in[15];
    const float* blin  = (const float*)d_in[16];
    float* out = (float*)d_out;

    int n = in_sizes[0];
    int E = in_sizes[1] / 2;
    if (n > NMAX) n = NMAX;
    if (E > EMAX) E = EMAX;

    const int TB = 256;
    int nPair = (E + 1) / 2;
    dim3 gEP((nPair + TB - 1) / TB);
    dim3 gNW(((size_t)n * 32 + TB - 1) / TB);
    int nTiles = (n + 127) / 128;
    int gemmGrid = (nTiles < GEMM_GRID) ? nTiles : GEMM_GRID;
    int nBlk = (n + 1023) / 1024;

    static cudaStream_t s2 = nullptr;
    static cudaEvent_t evFork = nullptr, evJoin = nullptr;
    if (!s2) {
        cudaStreamCreateWithFlags(&s2, cudaStreamNonBlocking);
        cudaEventCreateWithFlags(&evFork, cudaEventDisableTiming);
        cudaEventCreateWithFlags(&evJoin, cudaEventDisableTiming);
        cudaFuncSetAttribute(k_gemm_tc<0>, cudaFuncAttributeMaxDynamicSharedMemorySize, GEMM_SMEM);
        cudaFuncSetAttribute(k_gemm_tc<1>, cudaFuncAttributeMaxDynamicSharedMemorySize, GEMM_SMEM);
    }

    // fork: CSR build on s2; prep on main
    cudaEventRecord(evFork, 0);
    cudaStreamWaitEvent(s2, evFork, 0);

    k_hist<<<gEP, TB, 0, s2>>>(ei, E);
    k_scan<<<nBlk, 1024, 0, s2>>>(n, nBlk);
    k_scatter<<<gEP, TB, 0, s2>>>(ei, E);
    cudaEventRecord(evJoin, s2);

    k_prep<<<1, 256>>>(Wl[1], As[1], Ad[1], Wl[2], As[2], Ad[2]);

    cudaStreamWaitEvent(0, evJoin, 0);

    // layer 1: scalar agg + expand (writes h2 fp16 + layer-2 attn scalars)
    k_l1agg<<<gNW, TB>>>(x, Wl[0], As[0], Ad[0], Bs[0], n);
    // layer 2: wide agg -> fp16 GEMM (writes h3 fp16 + layer-3 attn scalars)
    k_gat_agg<<<gNW, TB>>>(n);
    k_gemm_tc<0><<<gemmGrid, TB, GEMM_SMEM>>>(Wl[1], Bs[1], g_cs + 256, g_cs + 384, batch, n);
    // layer 3: wide agg -> fp16 GEMM, pools directly
    k_gat_agg<<<gNW, TB>>>(n);
    k_gemm_tc<1><<<gemmGrid, TB, GEMM_SMEM>>>(Wl[2], Bs[2], nullptr, nullptr, batch, n);

    k_final<<<NG, 128>>>(Wlin, blin, out);
}

// round 15
// speedup vs baseline: 1.0996x; 1.0996x over previous
#include <cuda_runtime.h>
#include <cuda_fp16.h>
#include <math.h>
#include <stdint.h>

#define NMAX 50000
#define EMAX 600000
#define HID  128
#define NG   64
#define FULLMASK 0xffffffffu

#define PADH 136                               // halves per smem row
#define GEMM_SMEM (128 * PADH * 2 * 2)         // sWt + sA, fp16

// ---------------- device scratch ----------------
__device__ __align__(16) __half g_hh [(size_t)NMAX * HID];  // fp16 agg output (GEMM input)
__device__ __align__(16) __half g_xph[(size_t)NMAX * HID];  // fp16 gather payload (h_l)
__device__ float g_als[NMAX];
__device__ float g_ald[NMAX];
__device__ __align__(16) float g_pool[NG * HID + NG];       // pool + cnt (zeroed by k_final)
__device__ __align__(16) float g_cs[512];                   // cs2, cd2, cs3, cd3
__device__ int   g_deg[NMAX];                               // zeroed by k_scan_blk
__device__ int   g_rowptr[NMAX + 1];
__device__ int   g_wptr[NMAX];
__device__ int   g_csrc[EMAX];
__device__ int   g_bsum[64];

__device__ __forceinline__ float lrelu(float a) { return (a > 0.f) ? a : 0.2f * a; }

__device__ __forceinline__ void pdl_wait() {
    asm volatile("griddepcontrol.wait;" ::: "memory");
}

__device__ __forceinline__ void mma_f16(float c[4], const uint32_t a[4],
                                        uint32_t b0, uint32_t b1) {
    asm volatile(
        "mma.sync.aligned.m16n8k16.row.col.f32.f16.f16.f32 "
        "{%0,%1,%2,%3}, {%4,%5,%6,%7}, {%8,%9}, {%0,%1,%2,%3};"
        : "+f"(c[0]), "+f"(c[1]), "+f"(c[2]), "+f"(c[3])
        : "r"(a[0]), "r"(a[1]), "r"(a[2]), "r"(a[3]), "r"(b0), "r"(b1));
}

__device__ __forceinline__ float4 h4_to_f4(uint2 u) {
    float2 a = __half22float2(*(__half2*)&u.x);
    float2 b = __half22float2(*(__half2*)&u.y);
    return make_float4(a.x, a.y, b.x, b.y);
}

// ================= CSR build (stream s2) =================
__global__ void k_hist(const int* __restrict__ ei, int E) {
    int e = blockIdx.x * blockDim.x + threadIdx.x;
    if (e < E) atomicAdd(&g_deg[ei[E + e]], 1);
}

__global__ void k_scan_blk(int n) {
    __shared__ int warp_sums[32];
    int tid = threadIdx.x, lane = tid & 31, wid = tid >> 5;
    int i = blockIdx.x * 1024 + tid;
    int v = (i < n) ? g_deg[i] : 0;
    if (i < n) g_deg[i] = 0;          // restore zero-invariant
    int x = v;
#pragma unroll
    for (int o = 1; o < 32; o <<= 1) {
        int y = __shfl_up_sync(FULLMASK, x, o);
        if (lane >= o) x += y;
    }
    if (lane == 31) warp_sums[wid] = x;
    __syncthreads();
    if (wid == 0) {
        int w = warp_sums[lane];
#pragma unroll
        for (int o = 1; o < 32; o <<= 1) {
            int y = __shfl_up_sync(FULLMASK, w, o);
            if (lane >= o) w += y;
        }
        warp_sums[lane] = w;
    }
    __syncthreads();
    int excl = (wid ? warp_sums[wid - 1] : 0) + x - v;
    if (i < n) g_rowptr[i] = excl;
    if (tid == 1023) g_bsum[blockIdx.x] = warp_sums[31];
}

// fused top-scan + add (each block redundantly prefixes the <=64 block sums)
__global__ void k_scan_add(int n, int nb) {
    __shared__ int s_off, s_tot;
    if (threadIdx.x == 0) {
        int run = 0, off = 0;
        for (int b = 0; b < nb; b++) {
            if (b == (int)blockIdx.x) off = run;
            run += g_bsum[b];
        }
        s_off = off; s_tot = run;
    }
    __syncthreads();
    int i = blockIdx.x * 1024 + threadIdx.x;
    if (i < n) {
        int r = g_rowptr[i] + s_off;
        g_rowptr[i] = r;
        g_wptr[i] = r;
    }
    if (i == 0) g_rowptr[n] = s_tot;
}

__global__ void k_scatter(const int* __restrict__ ei, int E) {
    int e = blockIdx.x * blockDim.x + threadIdx.x;
    if (e >= E) return;
    int d = ei[E + e];
    int pos = atomicAdd(&g_wptr[d], 1);
    g_csrc[pos] = ei[e];
}

// ====== prep (parallel): cs_l = W_l@a_src_l, cd_l = W_l@a_dst_l (l=2,3) ======
// warp per output row; 256 warps = 32 blocks x 8 warps; coalesced float4 reads
__global__ void k_prep(const float* __restrict__ W2, const float* __restrict__ as2,
                       const float* __restrict__ ad2,
                       const float* __restrict__ W3, const float* __restrict__ as3,
                       const float* __restrict__ ad3) {
    int gw = (blockIdx.x * blockDim.x + threadIdx.x) >> 5;   // 0..255
    int lane = threadIdx.x & 31;
    if (gw >= 256) return;
    const float* W  = (gw < 128) ? W2 : W3;
    const float* av = (gw < 128) ? as2 : as3;
    const float* dv = (gw < 128) ? ad2 : ad3;
    int r = gw & 127;
    float4 w4 = *(const float4*)&W[r * 128 + lane * 4];
    float4 a4 = *(const float4*)&av[lane * 4];
    float4 d4 = *(const float4*)&dv[lane * 4];
    float s = w4.x * a4.x + w4.y * a4.y + w4.z * a4.z + w4.w * a4.w;
    float d = w4.x * d4.x + w4.y * d4.y + w4.z * d4.z + w4.w * d4.w;
#pragma unroll
    for (int o = 16; o > 0; o >>= 1) {
        s += __shfl_down_sync(FULLMASK, s, o);
        d += __shfl_down_sync(FULLMASK, d, o);
    }
    if (lane == 0) {
        int base = (gw < 128) ? 0 : 256;
        g_cs[base + r]       = s;
        g_cs[base + 128 + r] = d;
    }
}

// ================= layer 1: scalar agg (CSR) + expand + layer-2 attn scalars ========
__global__ __launch_bounds__(256) void k_l1agg(const float* __restrict__ x,
                                               const float* __restrict__ W1,
                                               const float* __restrict__ as1,
                                               const float* __restrict__ ad1,
                                               const float* __restrict__ b1, int n) {
    __shared__ float sc0, sc1;
    __shared__ float partS[4], partD[4];
    int tid = threadIdx.x;
    {
        float s = 0.f, d = 0.f;
        if (tid < 128) {
            float w = W1[tid];
            s = w * as1[tid];
            d = w * ad1[tid];
        }
#pragma unroll
        for (int o = 16; o > 0; o >>= 1) {
            s += __shfl_down_sync(FULLMASK, s, o);
            d += __shfl_down_sync(FULLMASK, d, o);
        }
        if (tid < 128 && (tid & 31) == 0) { partS[tid >> 5] = s; partD[tid >> 5] = d; }
        __syncthreads();
        if (tid == 0) sc0 = partS[0] + partS[1] + partS[2] + partS[3];
        if (tid == 1) sc1 = partD[0] + partD[1] + partD[2] + partD[3];
        __syncthreads();
    }
    int w = (blockIdx.x * blockDim.x + tid) >> 5;
    int lane = tid & 31;
    if (w >= n) return;
    float c0 = sc0, c1 = sc1;
    float xd = x[w];
    float ald_d = xd * c1;
    float a_self = lrelu(xd * c0 + ald_d);
    int row = g_rowptr[w], end = g_rowptr[w + 1];
    int cnt = end - row;
    float a1;

    if (cnt <= 32) {
        float xv = 0.f, a_reg = -1e30f;
        if (lane < cnt) {
            int s = g_csrc[row + lane];
            xv = x[s];
            a_reg = lrelu(xv * c0 + ald_d);
        }
        float m = fmaxf(a_reg, a_self);
#pragma unroll
        for (int o = 16; o > 0; o >>= 1)
            m = fmaxf(m, __shfl_xor_sync(FULLMASK, m, o));
        float p = (lane < cnt) ? __expf(a_reg - m) : 0.f;
        float num = p * xv, den = p;
#pragma unroll
        for (int o = 16; o > 0; o >>= 1) {
            num += __shfl_xor_sync(FULLMASK, num, o);
            den += __shfl_xor_sync(FULLMASK, den, o);
        }
        float eself = __expf(a_self - m);
        a1 = (num + eself * xd) / (den + eself);
    } else {
        float m = a_self;
        for (int e = row + lane; e < end; e += 32)
            m = fmaxf(m, lrelu(__ldg(&x[g_csrc[e]]) * c0 + ald_d));
#pragma unroll
        for (int o = 16; o > 0; o >>= 1)
            m = fmaxf(m, __shfl_xor_sync(FULLMASK, m, o));
        float num = 0.f, den = 0.f;
        for (int e = row + lane; e < end; e += 32) {
            float xv = __ldg(&x[g_csrc[e]]);
            float p = __expf(lrelu(xv * c0 + ald_d) - m);
            num += p * xv; den += p;
        }
#pragma unroll
        for (int o = 16; o > 0; o >>= 1) {
            num += __shfl_xor_sync(FULLMASK, num, o);
            den += __shfl_xor_sync(FULLMASK, den, o);
        }
        float eself = __expf(a_self - m);
        a1 = (num + eself * xd) / (den + eself);
    }

    float4 w4 = ((const float4*)W1)[lane];
    float4 b4 = ((const float4*)b1)[lane];
    float4 v;
    v.x = fmaxf(a1 * w4.x + b4.x, 0.f);
    v.y = fmaxf(a1 * w4.y + b4.y, 0.f);
    v.z = fmaxf(a1 * w4.z + b4.z, 0.f);
    v.w = fmaxf(a1 * w4.w + b4.w, 0.f);
    uint2 st;
    *(__half2*)&st.x = __floats2half2_rn(v.x, v.y);
    *(__half2*)&st.y = __floats2half2_rn(v.z, v.w);
    ((uint2*)g_xph)[(size_t)w * 32 + lane] = st;
    float4 cs4 = ((const float4*)g_cs)[lane];
    float4 cd4 = ((const float4*)(g_cs + 128))[lane];
    float ds = v.x * cs4.x + v.y * cs4.y + v.z * cs4.z + v.w * cs4.w;
    float dd = v.x * cd4.x + v.y * cd4.y + v.z * cd4.z + v.w * cd4.w;
#pragma unroll
    for (int o = 16; o > 0; o >>= 1) {
        ds += __shfl_down_sync(FULLMASK, ds, o);
        dd += __shfl_down_sync(FULLMASK, dd, o);
    }
    if (lane == 0) { g_als[w] = ds; g_ald[w] = dd; }
}

// ============ wide GAT softmax-aggregate (warp per dst node) -> fp16 g_hh ===========
__global__ __launch_bounds__(256) void k_gat_agg(int n) {
    int w = (blockIdx.x * blockDim.x + threadIdx.x) >> 5;
    int lane = threadIdx.x & 31;
    pdl_wait();   // predecessor (l1agg / gemm) must finish before reading als/ald/xph
    if (w >= n) return;
    int row = g_rowptr[w], end = g_rowptr[w + 1];
    int cnt = end - row;
    float ald_d = g_ald[w];
    float a_self = lrelu(g_als[w] + ald_d);
    const uint2* xpv = (const uint2*)g_xph;
    float4 acc;

    if (cnt <= 32) {
        int s_reg = 0;
        float a_reg = -1e30f;
        if (lane < cnt) {
            s_reg = g_csrc[row + lane];
            a_reg = lrelu(g_als[s_reg] + ald_d);
        }
        float m = fmaxf(a_reg, a_self);
#pragma unroll
        for (int o = 16; o > 0; o >>= 1)
            m = fmaxf(m, __shfl_xor_sync(FULLMASK, m, o));
        float p = (lane < cnt) ? __expf(a_reg - m) : 0.f;
        float den = p;
#pragma unroll
        for (int o = 16; o > 0; o >>= 1)
            den += __shfl_xor_sync(FULLMASK, den, o);
        float eself = __expf(a_self - m);
        float rden = 1.0f / (den + eself);
        p *= rden;

        float cself = eself * rden;
        float4 sv = h4_to_f4(xpv[(size_t)w * 32 + lane]);
        acc = make_float4(cself * sv.x, cself * sv.y, cself * sv.z, cself * sv.w);
        int j = 0;
        for (; j + 4 <= cnt; j += 4) {
            float c0 = __shfl_sync(FULLMASK, p, j + 0);
            float c1 = __shfl_sync(FULLMASK, p, j + 1);
            float c2 = __shfl_sync(FULLMASK, p, j + 2);
            float c3 = __shfl_sync(FULLMASK, p, j + 3);
            int s0 = __shfl_sync(FULLMASK, s_reg, j + 0);
            int s1 = __shfl_sync(FULLMASK, s_reg, j + 1);
            int s2 = __shfl_sync(FULLMASK, s_reg, j + 2);
            int s3 = __shfl_sync(FULLMASK, s_reg, j + 3);
            uint2 u0 = xpv[(size_t)s0 * 32 + lane];
            uint2 u1 = xpv[(size_t)s1 * 32 + lane];
            uint2 u2 = xpv[(size_t)s2 * 32 + lane];
            uint2 u3 = xpv[(size_t)s3 * 32 + lane];
            float4 v0 = h4_to_f4(u0), v1 = h4_to_f4(u1);
            float4 v2 = h4_to_f4(u2), v3 = h4_to_f4(u3);
            acc.x += c0 * v0.x + c1 * v1.x + c2 * v2.x + c3 * v3.x;
            acc.y += c0 * v0.y + c1 * v1.y + c2 * v2.y + c3 * v3.y;
            acc.z += c0 * v0.z + c1 * v1.z + c2 * v2.z + c3 * v3.z;
            acc.w += c0 * v0.w + c1 * v1.w + c2 * v2.w + c3 * v3.w;
        }
        for (; j < cnt; j++) {
            float coef = __shfl_sync(FULLMASK, p, j);
            int s = __shfl_sync(FULLMASK, s_reg, j);
            float4 v = h4_to_f4(xpv[(size_t)s * 32 + lane]);
            acc.x += coef * v.x; acc.y += coef * v.y;
            acc.z += coef * v.z; acc.w += coef * v.w;
        }
    } else {
        float m = a_self;
        for (int e = row + lane; e < end; e += 32)
            m = fmaxf(m, lrelu(__ldg(&g_als[g_csrc[e]]) + ald_d));
#pragma unroll
        for (int o = 16; o > 0; o >>= 1)
            m = fmaxf(m, __shfl_xor_sync(FULLMASK, m, o));
        float den = (lane == 0) ? __expf(a_self - m) : 0.f;
        for (int e = row + lane; e < end; e += 32)
            den += __expf(lrelu(__ldg(&g_als[g_csrc[e]]) + ald_d) - m);
#pragma unroll
        for (int o = 16; o > 0; o >>= 1)
            den += __shfl_xor_sync(FULLMASK, den, o);
        float rden = 1.0f / den;
        float cself = __expf(a_self - m) * rden;
        float4 sv = h4_to_f4(xpv[(size_t)w * 32 + lane]);
        acc = make_float4(cself * sv.x, cself * sv.y, cself * sv.z, cself * sv.w);
        for (int j = row; j < end; j++) {
            int s = g_csrc[j];
            float coef = __expf(lrelu(g_als[s] + ald_d) - m) * rden;
            float4 v = h4_to_f4(xpv[(size_t)s * 32 + lane]);
            acc.x += coef * v.x; acc.y += coef * v.y;
            acc.z += coef * v.z; acc.w += coef * v.w;
        }
    }
    uint2 st;
    *(__half2*)&st.x = __floats2half2_rn(acc.x, acc.y);
    *(__half2*)&st.y = __floats2half2_rn(acc.z, acc.w);
    ((uint2*)g_hh)[(size_t)w * 32 + lane] = st;
}

// ============ fp16 HMMA GEMM: out = g_hh @ W; h_next = relu(out + b) ===============
// PDL: W staging (input-only) runs before griddepcontrol.wait -> overlaps agg tail.
template <int FINAL>
__global__ __launch_bounds__(256, 2) void k_gemm_tc(const float* __restrict__ W,
                                                    const float* __restrict__ bias,
                                                    const float* __restrict__ csv,
                                                    const float* __restrict__ cdv,
                                                    const int* __restrict__ batch, int n) {
    extern __shared__ __half smem_h[];
    __half* sWt = smem_h;                  // [128 n][PADH k] transposed fp16
    __half* sA  = smem_h + 128 * PADH;     // [128 row][PADH k] fp16
    __shared__ float sS[128], sD[128];

    const int tid = threadIdx.x;
    const int row0 = blockIdx.x * 128;
    const int wid = tid >> 5, lane = tid & 31;
    const int wr = wid & 3;
    const int wc = wid >> 2;
    const int gid = lane >> 2, tig = lane & 3;

    if (FINAL == 0 && tid < 128) { sS[tid] = 0.f; sD[tid] = 0.f; }

    // stage W transposed to fp16 (independent of predecessor output)
    for (int i = tid; i < 4096; i += 256) {
        int nn = i & 127;
        int k4 = i >> 7;
        float w0 = W[(k4 * 4 + 0) * 128 + nn];
        float w1 = W[(k4 * 4 + 1) * 128 + nn];
        float w2 = W[(k4 * 4 + 2) * 128 + nn];
        float w3 = W[(k4 * 4 + 3) * 128 + nn];
        __half2* dst = (__half2*)&sWt[nn * PADH + k4 * 4];
        dst[0] = __floats2half2_rn(w0, w1);
        dst[1] = __floats2half2_rn(w2, w3);
    }

    pdl_wait();   // now safe to read g_hh written by predecessor agg

    // stage A (straight fp16 copy, 16B chunks)
    {
        const uint4* src = (const uint4*)g_hh;
        for (int idx = tid; idx < 2048; idx += 256) {
            int r = idx >> 4;
            int c = idx & 15;
            uint4 v = make_uint4(0u, 0u, 0u, 0u);
            if (row0 + r < n) v = src[(size_t)(row0 + r) * 16 + c];
            *(uint4*)&sA[r * PADH + c * 8] = v;
        }
    }
    __syncthreads();

    float acc[2][8][4];
#pragma unroll
    for (int mt = 0; mt < 2; mt++)
#pragma unroll
        for (int j = 0; j < 8; j++)
#pragma unroll
            for (int q = 0; q < 4; q++) acc[mt][j][q] = 0.f;

#pragma unroll
    for (int ks = 0; ks < 8; ks++) {
        int k0 = ks * 16;
        uint32_t a[2][4];
#pragma unroll
        for (int mt = 0; mt < 2; mt++) {
            int base = wr * 32 + mt * 16;
            a[mt][0] = *(uint32_t*)&sA[(base + gid)     * PADH + k0 + tig * 2];
            a[mt][1] = *(uint32_t*)&sA[(base + gid + 8) * PADH + k0 + tig * 2];
            a[mt][2] = *(uint32_t*)&sA[(base + gid)     * PADH + k0 + tig * 2 + 8];
            a[mt][3] = *(uint32_t*)&sA[(base + gid + 8) * PADH + k0 + tig * 2 + 8];
        }
#pragma unroll
        for (int j = 0; j < 8; j++) {
            int col = wc * 64 + j * 8 + gid;
            uint32_t b0 = *(uint32_t*)&sWt[col * PADH + k0 + tig * 2];
            uint32_t b1 = *(uint32_t*)&sWt[col * PADH + k0 + tig * 2 + 8];
            mma_f16(acc[0][j], a[0], b0, b1);
            mma_f16(acc[1][j], a[1], b0, b1);
        }
    }
    __syncthreads();

#pragma unroll
    for (int mt = 0; mt < 2; mt++) {
        int lr0 = wr * 32 + mt * 16 + gid;
        int lr1 = lr0 + 8;
        int r0 = row0 + lr0, r1 = row0 + lr1;
        int gg0 = 0, gg1 = 0;
        if (FINAL == 1) {
            gg0 = (r0 < n) ? batch[r0] : 0;
            gg1 = (r1 < n) ? batch[r1] : 0;
        }
        float ps0 = 0.f, pd0 = 0.f, ps1 = 0.f, pd1 = 0.f;
#pragma unroll
        for (int j = 0; j < 8; j++) {
            int col = wc * 64 + j * 8 + tig * 2;
            float bb0 = __ldg(&bias[col]), bb1 = __ldg(&bias[col + 1]);
            float v00 = fmaxf(acc[mt][j][0] + bb0, 0.f);
            float v01 = fmaxf(acc[mt][j][1] + bb1, 0.f);
            float v10 = fmaxf(acc[mt][j][2] + bb0, 0.f);
            float v11 = fmaxf(acc[mt][j][3] + bb1, 0.f);
            if (FINAL == 0) {
                float av0 = __ldg(&csv[col]), av1 = __ldg(&csv[col + 1]);
                float dv0 = __ldg(&cdv[col]), dv1 = __ldg(&cdv[col + 1]);
                if (r0 < n)
                    *(__half2*)&g_xph[(size_t)r0 * 128 + col] = __floats2half2_rn(v00, v01);
                if (r1 < n)
                    *(__half2*)&g_xph[(size_t)r1 * 128 + col] = __floats2half2_rn(v10, v11);
                ps0 += v00 * av0 + v01 * av1;
                pd0 += v00 * dv0 + v01 * dv1;
                ps1 += v10 * av0 + v11 * av1;
                pd1 += v10 * dv0 + v11 * dv1;
            } else {
                float n00 = __shfl_xor_sync(FULLMASK, v00, 1);
                float n01 = __shfl_xor_sync(FULLMASK, v01, 1);
                float n10 = __shfl_xor_sync(FULLMASK, v10, 1);
                float n11 = __shfl_xor_sync(FULLMASK, v11, 1);
                if ((tig & 1) == 0) {
                    int cb = wc * 64 + j * 8 + tig * 2;
                    if (r0 < n)
                        atomicAdd((float4*)&g_pool[gg0 * 128 + cb],
                                  make_float4(v00, v01, n00, n01));
                    if (r1 < n)
                        atomicAdd((float4*)&g_pool[gg1 * 128 + cb],
                                  make_float4(v10, v11, n10, n11));
                }
            }
        }
        if (FINAL == 0) {
            atomicAdd(&sS[lr0], ps0); atomicAdd(&sD[lr0], pd0);
            atomicAdd(&sS[lr1], ps1); atomicAdd(&sD[lr1], pd1);
        } else if (wc == 0 && tig == 0) {
            if (r0 < n) atomicAdd(&g_pool[NG * HID + gg0], 1.0f);
            if (r1 < n) atomicAdd(&g_pool[NG * HID + gg1], 1.0f);
        }
    }
    if (FINAL == 0) {
        __syncthreads();
        if (tid < 128 && row0 + tid < n) {
            g_als[row0 + tid] = sS[tid];
            g_ald[row0 + tid] = sD[tid];
        }
    }
}

// ================= head (re-zeroes g_pool for next replay) =================
__global__ void k_final(const float* __restrict__ Wlin, const float* __restrict__ blin,
                        float* __restrict__ out) {
    int g = blockIdx.x;
    int j = threadIdx.x;
    __shared__ float s0[128], s1[128];
    float w0 = Wlin[j * 2 + 0];   // input-only prologue
    float w1 = Wlin[j * 2 + 1];
    pdl_wait();                   // g_pool written by gemm3
    float cnt = fmaxf(g_pool[NG * HID + g], 1.0f);
    float p = g_pool[g * 128 + j] / cnt;
    s0[j] = p * w0;
    s1[j] = p * w1;
    __syncthreads();
    g_pool[g * 128 + j] = 0.f;
    if (j == 0) g_pool[NG * HID + g] = 0.f;
#pragma unroll
    for (int st = 64; st > 0; st >>= 1) {
        if (j < st) { s0[j] += s0[j + st]; s1[j] += s1[j + st]; }
        __syncthreads();
    }
    if (j == 0) {
        out[g * 2 + 0] = 1.0f / (1.0f + __expf(-(s0[0] + blin[0])));
        out[g * 2 + 1] = 1.0f / (1.0f + __expf(-(s1[0] + blin[1])));
    }
}

// ================= host =================
extern "C" void kernel_launch(void* const* d_in, const int* in_sizes, int n_in,
                              void* d_out, int out_size) {
    const float* x     = (const float*)d_in[0];
    const int*   ei    = (const int*)d_in[1];
    const int*   batch = (const int*)d_in[2];
    const float* Wl[3] = { (const float*)d_in[3], (const float*)d_in[7],  (const float*)d_in[11] };
    const float* As[3] = { (const float*)d_in[4], (const float*)d_in[8],  (const float*)d_in[12] };
    const float* Ad[3] = { (const float*)d_in[5], (const float*)d_in[9],  (const float*)d_in[13] };
    const float* Bs[3] = { (const float*)d_in[6], (const float*)d_in[10], (const float*)d_in[14] };
    const float* Wlin  = (const float*)d_in[15];
    const float* blin  = (const float*)d_in[16];
    float* out = (float*)d_out;

    int n = in_sizes[0];
    int E = in_sizes[1] / 2;
    if (n > NMAX) n = NMAX;
    if (E > EMAX) E = EMAX;

    const int TB = 256;
    dim3 gE((E + TB - 1) / TB);
    dim3 gNW(((size_t)n * 32 + TB - 1) / TB);
    dim3 gG((n + 127) / 128);
    int nBlk = (n + 1023) / 1024;

    static cudaStream_t s2 = nullptr;
    static cudaEvent_t evFork = nullptr, evJoin = nullptr;
    if (!s2) {
        cudaStreamCreateWithFlags(&s2, cudaStreamNonBlocking);
        cudaEventCreateWithFlags(&evFork, cudaEventDisableTiming);
        cudaEventCreateWithFlags(&evJoin, cudaEventDisableTiming);
        cudaFuncSetAttribute(k_gemm_tc<0>, cudaFuncAttributeMaxDynamicSharedMemorySize, GEMM_SMEM);
        cudaFuncSetAttribute(k_gemm_tc<1>, cudaFuncAttributeMaxDynamicSharedMemorySize, GEMM_SMEM);
    }

    // PDL launch config helper
    cudaLaunchAttribute pdlAttr[1];
    pdlAttr[0].id = cudaLaunchAttributeProgrammaticStreamSerialization;
    pdlAttr[0].val.programmaticStreamSerializationAllowed = 1;

    // fork: CSR build on s2; prep on main
    cudaEventRecord(evFork, 0);
    cudaStreamWaitEvent(s2, evFork, 0);

    k_hist<<<gE, TB, 0, s2>>>(ei, E);
    k_scan_blk<<<nBlk, 1024, 0, s2>>>(n);
    k_scan_add<<<nBlk, 1024, 0, s2>>>(n, nBlk);
    k_scatter<<<gE, TB, 0, s2>>>(ei, E);
    cudaEventRecord(evJoin, s2);

    k_prep<<<32, 256>>>(Wl[1], As[1], Ad[1], Wl[2], As[2], Ad[2]);

    cudaStreamWaitEvent(0, evJoin, 0);

    // layer 1: scalar agg + expand (regular launch — follows cross-stream join)
    k_l1agg<<<gNW, TB>>>(x, Wl[0], As[0], Ad[0], Bs[0], n);

    // layer 2: wide agg -> fp16 GEMM (PDL chain)
    {
        cudaLaunchConfig_t cfg = {};
        cfg.gridDim = gNW; cfg.blockDim = dim3(TB);
        cfg.attrs = pdlAttr; cfg.numAttrs = 1;
        cudaLaunchKernelEx(&cfg, k_gat_agg, n);
    }
    {
        cudaLaunchConfig_t cfg = {};
        cfg.gridDim = gG; cfg.blockDim = dim3(TB);
        cfg.dynamicSmemBytes = GEMM_SMEM;
        cfg.attrs = pdlAttr; cfg.numAttrs = 1;
        cudaLaunchKernelEx(&cfg, k_gemm_tc<0>, Wl[1], Bs[1],
                           (const float*)(g_cs + 256), (const float*)(g_cs + 384), batch, n);
    }
    // layer 3: wide agg -> fp16 GEMM (pools directly)
    {
        cudaLaunchConfig_t cfg = {};
        cfg.gridDim = gNW; cfg.blockDim = dim3(TB);
        cfg.attrs = pdlAttr; cfg.numAttrs = 1;
        cudaLaunchKernelEx(&cfg, k_gat_agg, n);
    }
    {
        cudaLaunchConfig_t cfg = {};
        cfg.gridDim = gG; cfg.blockDim = dim3(TB);
        cfg.dynamicSmemBytes = GEMM_SMEM;
        cfg.attrs = pdlAttr; cfg.numAttrs = 1;
        cudaLaunchKernelEx(&cfg, k_gemm_tc<1>, Wl[2], Bs[2],
                           (const float*)nullptr, (const float*)nullptr, batch, n);
    }
    {
        cudaLaunchConfig_t cfg = {};
        cfg.gridDim = dim3(NG); cfg.blockDim = dim3(128);
        cfg.attrs = pdlAttr; cfg.numAttrs = 1;
        cudaLaunchKernelEx(&cfg, k_final, Wlin, blin, out);
    }
}

// round 16
// speedup vs baseline: 1.1032x; 1.0032x over previous
#include <cuda_runtime.h>
#include <cuda_fp16.h>
#include <math.h>
#include <stdint.h>

#define NMAX 50000
#define EMAX 600000
#define HID  128
#define NG   64
#define FULLMASK 0xffffffffu

#define PADH 136                               // halves per smem row
#define GEMM_SMEM (128 * PADH * 2 * 2)         // sWt + sA, fp16

// ---------------- device scratch ----------------
__device__ __align__(16) __half g_hh [(size_t)NMAX * HID];  // fp16 agg output (GEMM input)
__device__ __align__(16) __half g_xph[(size_t)NMAX * HID];  // fp16 gather payload (h_l)
__device__ float g_als[NMAX];
__device__ float g_ald[NMAX];
__device__ __align__(16) float g_pool[NG * HID + NG];       // pool + cnt (zeroed by k_final)
__device__ __align__(16) float g_cs[512];                   // cs2, cd2, cs3, cd3
__device__ int   g_deg[NMAX];                               // zeroed by k_scan_blk
__device__ int   g_rowptr[NMAX + 1];
__device__ int   g_wptr[NMAX];
__device__ int   g_csrc[EMAX];
__device__ int   g_bsum[64];

__device__ __forceinline__ float lrelu(float a) { return (a > 0.f) ? a : 0.2f * a; }

__device__ __forceinline__ void pdl_wait() {
    asm volatile("griddepcontrol.wait;" ::: "memory");
}

__device__ __forceinline__ void mma_f16(float c[4], const uint32_t a[4],
                                        uint32_t b0, uint32_t b1) {
    asm volatile(
        "mma.sync.aligned.m16n8k16.row.col.f32.f16.f16.f32 "
        "{%0,%1,%2,%3}, {%4,%5,%6,%7}, {%8,%9}, {%0,%1,%2,%3};"
        : "+f"(c[0]), "+f"(c[1]), "+f"(c[2]), "+f"(c[3])
        : "r"(a[0]), "r"(a[1]), "r"(a[2]), "r"(a[3]), "r"(b0), "r"(b1));
}

__device__ __forceinline__ float4 h4_to_f4(uint2 u) {
    float2 a = __half22float2(*(__half2*)&u.x);
    float2 b = __half22float2(*(__half2*)&u.y);
    return make_float4(a.x, a.y, b.x, b.y);
}

// ================= CSR build (stream s2, PDL-chained) =================
__global__ void k_hist(const int* __restrict__ ei, int E) {
    int e = blockIdx.x * blockDim.x + threadIdx.x;
    if (e < E) atomicAdd(&g_deg[ei[E + e]], 1);
}

__global__ void k_scan_blk(int n) {
    __shared__ int warp_sums[32];
    int tid = threadIdx.x, lane = tid & 31, wid = tid >> 5;
    int i = blockIdx.x * 1024 + tid;
    pdl_wait();                        // hist atomics must be visible
    int v = (i < n) ? g_deg[i] : 0;
    if (i < n) g_deg[i] = 0;           // restore zero-invariant
    int x = v;
#pragma unroll
    for (int o = 1; o < 32; o <<= 1) {
        int y = __shfl_up_sync(FULLMASK, x, o);
        if (lane >= o) x += y;
    }
    if (lane == 31) warp_sums[wid] = x;
    __syncthreads();
    if (wid == 0) {
        int w = warp_sums[lane];
#pragma unroll
        for (int o = 1; o < 32; o <<= 1) {
            int y = __shfl_up_sync(FULLMASK, w, o);
            if (lane >= o) w += y;
        }
        warp_sums[lane] = w;
    }
    __syncthreads();
    int excl = (wid ? warp_sums[wid - 1] : 0) + x - v;
    if (i < n) g_rowptr[i] = excl;
    if (tid == 1023) g_bsum[blockIdx.x] = warp_sums[31];
}

// fused top-scan + add (each block redundantly prefixes the <=64 block sums)
__global__ void k_scan_add(int n, int nb) {
    __shared__ int s_off, s_tot;
    pdl_wait();                        // g_bsum / g_rowptr from scan_blk
    if (threadIdx.x == 0) {
        int run = 0, off = 0;
        for (int b = 0; b < nb; b++) {
            if (b == (int)blockIdx.x) off = run;
            run += g_bsum[b];
        }
        s_off = off; s_tot = run;
    }
    __syncthreads();
    int i = blockIdx.x * 1024 + threadIdx.x;
    if (i < n) {
        int r = g_rowptr[i] + s_off;
        g_rowptr[i] = r;
        g_wptr[i] = r;
    }
    if (i == 0) g_rowptr[n] = s_tot;
}

__global__ void k_scatter(const int* __restrict__ ei, int E) {
    int e = blockIdx.x * blockDim.x + threadIdx.x;
    // prologue: input-only loads stream in under scan_add (PDL)
    int s = 0, d = 0;
    if (e < E) { s = ei[e]; d = ei[E + e]; }
    pdl_wait();                        // g_wptr from scan_add
    if (e >= E) return;
    int pos = atomicAdd(&g_wptr[d], 1);
    g_csrc[pos] = s;
}

// ====== prep (parallel): cs_l = W_l@a_src_l, cd_l = W_l@a_dst_l (l=2,3) ======
__global__ void k_prep(const float* __restrict__ W2, const float* __restrict__ as2,
                       const float* __restrict__ ad2,
                       const float* __restrict__ W3, const float* __restrict__ as3,
                       const float* __restrict__ ad3) {
    int gw = (blockIdx.x * blockDim.x + threadIdx.x) >> 5;   // 0..255
    int lane = threadIdx.x & 31;
    if (gw >= 256) return;
    const float* W  = (gw < 128) ? W2 : W3;
    const float* av = (gw < 128) ? as2 : as3;
    const float* dv = (gw < 128) ? ad2 : ad3;
    int r = gw & 127;
    float4 w4 = *(const float4*)&W[r * 128 + lane * 4];
    float4 a4 = *(const float4*)&av[lane * 4];
    float4 d4 = *(const float4*)&dv[lane * 4];
    float s = w4.x * a4.x + w4.y * a4.y + w4.z * a4.z + w4.w * a4.w;
    float d = w4.x * d4.x + w4.y * d4.y + w4.z * d4.z + w4.w * d4.w;
#pragma unroll
    for (int o = 16; o > 0; o >>= 1) {
        s += __shfl_down_sync(FULLMASK, s, o);
        d += __shfl_down_sync(FULLMASK, d, o);
    }
    if (lane == 0) {
        int base = (gw < 128) ? 0 : 256;
        g_cs[base + r]       = s;
        g_cs[base + 128 + r] = d;
    }
}

// ================= layer 1: scalar agg (CSR) + expand + layer-2 attn scalars ========
__global__ __launch_bounds__(256) void k_l1agg(const float* __restrict__ x,
                                               const float* __restrict__ W1,
                                               const float* __restrict__ as1,
                                               const float* __restrict__ ad1,
                                               const float* __restrict__ b1, int n) {
    __shared__ float sc0, sc1;
    __shared__ float partS[4], partD[4];
    int tid = threadIdx.x;
    {
        float s = 0.f, d = 0.f;
        if (tid < 128) {
            float w = W1[tid];
            s = w * as1[tid];
            d = w * ad1[tid];
        }
#pragma unroll
        for (int o = 16; o > 0; o >>= 1) {
            s += __shfl_down_sync(FULLMASK, s, o);
            d += __shfl_down_sync(FULLMASK, d, o);
        }
        if (tid < 128 && (tid & 31) == 0) { partS[tid >> 5] = s; partD[tid >> 5] = d; }
        __syncthreads();
        if (tid == 0) sc0 = partS[0] + partS[1] + partS[2] + partS[3];
        if (tid == 1) sc1 = partD[0] + partD[1] + partD[2] + partD[3];
        __syncthreads();
    }
    int w = (blockIdx.x * blockDim.x + tid) >> 5;
    int lane = tid & 31;
    if (w >= n) return;
    float c0 = sc0, c1 = sc1;
    float xd = x[w];
    float ald_d = xd * c1;
    float a_self = lrelu(xd * c0 + ald_d);
    int row = g_rowptr[w], end = g_rowptr[w + 1];
    int cnt = end - row;
    float a1;

    if (cnt <= 32) {
        float xv = 0.f, a_reg = -1e30f;
        if (lane < cnt) {
            int s = g_csrc[row + lane];
            xv = x[s];
            a_reg = lrelu(xv * c0 + ald_d);
        }
        float m = fmaxf(a_reg, a_self);
#pragma unroll
        for (int o = 16; o > 0; o >>= 1)
            m = fmaxf(m, __shfl_xor_sync(FULLMASK, m, o));
        float p = (lane < cnt) ? __expf(a_reg - m) : 0.f;
        float num = p * xv, den = p;
#pragma unroll
        for (int o = 16; o > 0; o >>= 1) {
            num += __shfl_xor_sync(FULLMASK, num, o);
            den += __shfl_xor_sync(FULLMASK, den, o);
        }
        float eself = __expf(a_self - m);
        a1 = (num + eself * xd) / (den + eself);
    } else {
        float m = a_self;
        for (int e = row + lane; e < end; e += 32)
            m = fmaxf(m, lrelu(__ldg(&x[g_csrc[e]]) * c0 + ald_d));
#pragma unroll
        for (int o = 16; o > 0; o >>= 1)
            m = fmaxf(m, __shfl_xor_sync(FULLMASK, m, o));
        float num = 0.f, den = 0.f;
        for (int e = row + lane; e < end; e += 32) {
            float xv = __ldg(&x[g_csrc[e]]);
            float p = __expf(lrelu(xv * c0 + ald_d) - m);
            num += p * xv; den += p;
        }
#pragma unroll
        for (int o = 16; o > 0; o >>= 1) {
            num += __shfl_xor_sync(FULLMASK, num, o);
            den += __shfl_xor_sync(FULLMASK, den, o);
        }
        float eself = __expf(a_self - m);
        a1 = (num + eself * xd) / (den + eself);
    }

    float4 w4 = ((const float4*)W1)[lane];
    float4 b4 = ((const float4*)b1)[lane];
    float4 v;
    v.x = fmaxf(a1 * w4.x + b4.x, 0.f);
    v.y = fmaxf(a1 * w4.y + b4.y, 0.f);
    v.z = fmaxf(a1 * w4.z + b4.z, 0.f);
    v.w = fmaxf(a1 * w4.w + b4.w, 0.f);
    uint2 st;
    *(__half2*)&st.x = __floats2half2_rn(v.x, v.y);
    *(__half2*)&st.y = __floats2half2_rn(v.z, v.w);
    ((uint2*)g_xph)[(size_t)w * 32 + lane] = st;
    float4 cs4 = ((const float4*)g_cs)[lane];
    float4 cd4 = ((const float4*)(g_cs + 128))[lane];
    float ds = v.x * cs4.x + v.y * cs4.y + v.z * cs4.z + v.w * cs4.w;
    float dd = v.x * cd4.x + v.y * cd4.y + v.z * cd4.z + v.w * cd4.w;
#pragma unroll
    for (int o = 16; o > 0; o >>= 1) {
        ds += __shfl_down_sync(FULLMASK, ds, o);
        dd += __shfl_down_sync(FULLMASK, dd, o);
    }
    if (lane == 0) { g_als[w] = ds; g_ald[w] = dd; }
}

// ============ wide GAT softmax-aggregate (warp per dst node) -> fp16 g_hh ===========
__global__ __launch_bounds__(256) void k_gat_agg(int n) {
    int w = (blockIdx.x * blockDim.x + threadIdx.x) >> 5;
    int lane = threadIdx.x & 31;
    pdl_wait();   // predecessor (l1agg / gemm) must finish before reading als/ald/xph
    if (w >= n) return;
    int row = g_rowptr[w], end = g_rowptr[w + 1];
    int cnt = end - row;
    float ald_d = g_ald[w];
    float a_self = lrelu(g_als[w] + ald_d);
    const uint2* xpv = (const uint2*)g_xph;
    float4 acc;

    if (cnt <= 32) {
        int s_reg = 0;
        float a_reg = -1e30f;
        if (lane < cnt) {
            s_reg = g_csrc[row + lane];
            a_reg = lrelu(g_als[s_reg] + ald_d);
        }
        float m = fmaxf(a_reg, a_self);
#pragma unroll
        for (int o = 16; o > 0; o >>= 1)
            m = fmaxf(m, __shfl_xor_sync(FULLMASK, m, o));
        float p = (lane < cnt) ? __expf(a_reg - m) : 0.f;
        float den = p;
#pragma unroll
        for (int o = 16; o > 0; o >>= 1)
            den += __shfl_xor_sync(FULLMASK, den, o);
        float eself = __expf(a_self - m);
        float rden = 1.0f / (den + eself);
        p *= rden;

        float cself = eself * rden;
        float4 sv = h4_to_f4(xpv[(size_t)w * 32 + lane]);
        acc = make_float4(cself * sv.x, cself * sv.y, cself * sv.z, cself * sv.w);
        int j = 0;
        for (; j + 4 <= cnt; j += 4) {
            float c0 = __shfl_sync(FULLMASK, p, j + 0);
            float c1 = __shfl_sync(FULLMASK, p, j + 1);
            float c2 = __shfl_sync(FULLMASK, p, j + 2);
            float c3 = __shfl_sync(FULLMASK, p, j + 3);
            int s0 = __shfl_sync(FULLMASK, s_reg, j + 0);
            int s1 = __shfl_sync(FULLMASK, s_reg, j + 1);
            int s2 = __shfl_sync(FULLMASK, s_reg, j + 2);
            int s3 = __shfl_sync(FULLMASK, s_reg, j + 3);
            uint2 u0 = xpv[(size_t)s0 * 32 + lane];
            uint2 u1 = xpv[(size_t)s1 * 32 + lane];
            uint2 u2 = xpv[(size_t)s2 * 32 + lane];
            uint2 u3 = xpv[(size_t)s3 * 32 + lane];
            float4 v0 = h4_to_f4(u0), v1 = h4_to_f4(u1);
            float4 v2 = h4_to_f4(u2), v3 = h4_to_f4(u3);
            acc.x += c0 * v0.x + c1 * v1.x + c2 * v2.x + c3 * v3.x;
            acc.y += c0 * v0.y + c1 * v1.y + c2 * v2.y + c3 * v3.y;
            acc.z += c0 * v0.z + c1 * v1.z + c2 * v2.z + c3 * v3.z;
            acc.w += c0 * v0.w + c1 * v1.w + c2 * v2.w + c3 * v3.w;
        }
        for (; j < cnt; j++) {
            float coef = __shfl_sync(FULLMASK, p, j);
            int s = __shfl_sync(FULLMASK, s_reg, j);
            float4 v = h4_to_f4(xpv[(size_t)s * 32 + lane]);
            acc.x += coef * v.x; acc.y += coef * v.y;
            acc.z += coef * v.z; acc.w += coef * v.w;
        }
    } else {
        float m = a_self;
        for (int e = row + lane; e < end; e += 32)
            m = fmaxf(m, lrelu(__ldg(&g_als[g_csrc[e]]) + ald_d));
#pragma unroll
        for (int o = 16; o > 0; o >>= 1)
            m = fmaxf(m, __shfl_xor_sync(FULLMASK, m, o));
        float den = (lane == 0) ? __expf(a_self - m) : 0.f;
        for (int e = row + lane; e < end; e += 32)
            den += __expf(lrelu(__ldg(&g_als[g_csrc[e]]) + ald_d) - m);
#pragma unroll
        for (int o = 16; o > 0; o >>= 1)
            den += __shfl_xor_sync(FULLMASK, den, o);
        float rden = 1.0f / den;
        float cself = __expf(a_self - m) * rden;
        float4 sv = h4_to_f4(xpv[(size_t)w * 32 + lane]);
        acc = make_float4(cself * sv.x, cself * sv.y, cself * sv.z, cself * sv.w);
        for (int j = row; j < end; j++) {
            int s = g_csrc[j];
            float coef = __expf(lrelu(g_als[s] + ald_d) - m) * rden;
            float4 v = h4_to_f4(xpv[(size_t)s * 32 + lane]);
            acc.x += coef * v.x; acc.y += coef * v.y;
            acc.z += coef * v.z; acc.w += coef * v.w;
        }
    }
    uint2 st;
    *(__half2*)&st.x = __floats2half2_rn(acc.x, acc.y);
    *(__half2*)&st.y = __floats2half2_rn(acc.z, acc.w);
    ((uint2*)g_hh)[(size_t)w * 32 + lane] = st;
}

// ============ fp16 HMMA GEMM: out = g_hh @ W; h_next = relu(out + b) ===============
// PDL: W staging (input-only) runs before griddepcontrol.wait -> overlaps agg tail.
template <int FINAL>
__global__ __launch_bounds__(256, 2) void k_gemm_tc(const float* __restrict__ W,
                                                    const float* __restrict__ bias,
                                                    const float* __restrict__ csv,
                                                    const float* __restrict__ cdv,
                                                    const int* __restrict__ batch, int n) {
    extern __shared__ __half smem_h[];
    __half* sWt = smem_h;                  // [128 n][PADH k] transposed fp16
    __half* sA  = smem_h + 128 * PADH;     // [128 row][PADH k] fp16
    __shared__ float sS[128], sD[128];

    const int tid = threadIdx.x;
    const int row0 = blockIdx.x * 128;
    const int wid = tid >> 5, lane = tid & 31;
    const int wr = wid & 3;
    const int wc = wid >> 2;
    const int gid = lane >> 2, tig = lane & 3;

    if (FINAL == 0 && tid < 128) { sS[tid] = 0.f; sD[tid] = 0.f; }

    // stage W transposed to fp16 (independent of predecessor output)
    for (int i = tid; i < 4096; i += 256) {
        int nn = i & 127;
        int k4 = i >> 7;
        float w0 = W[(k4 * 4 + 0) * 128 + nn];
        float w1 = W[(k4 * 4 + 1) * 128 + nn];
        float w2 = W[(k4 * 4 + 2) * 128 + nn];
        float w3 = W[(k4 * 4 + 3) * 128 + nn];
        __half2* dst = (__half2*)&sWt[nn * PADH + k4 * 4];
        dst[0] = __floats2half2_rn(w0, w1);
        dst[1] = __floats2half2_rn(w2, w3);
    }

    pdl_wait();   // now safe to read g_hh written by predecessor agg

    // stage A (straight fp16 copy, 16B chunks)
    {
        const uint4* src = (const uint4*)g_hh;
        for (int idx = tid; idx < 2048; idx += 256) {
            int r = idx >> 4;
            int c = idx & 15;
            uint4 v = make_uint4(0u, 0u, 0u, 0u);
            if (row0 + r < n) v = src[(size_t)(row0 + r) * 16 + c];
            *(uint4*)&sA[r * PADH + c * 8] = v;
        }
    }
    __syncthreads();

    float acc[2][8][4];
#pragma unroll
    for (int mt = 0; mt < 2; mt++)
#pragma unroll
        for (int j = 0; j < 8; j++)
#pragma unroll
            for (int q = 0; q < 4; q++) acc[mt][j][q] = 0.f;

#pragma unroll
    for (int ks = 0; ks < 8; ks++) {
        int k0 = ks * 16;
        uint32_t a[2][4];
#pragma unroll
        for (int mt = 0; mt < 2; mt++) {
            int base = wr * 32 + mt * 16;
            a[mt][0] = *(uint32_t*)&sA[(base + gid)     * PADH + k0 + tig * 2];
            a[mt][1] = *(uint32_t*)&sA[(base + gid + 8) * PADH + k0 + tig * 2];
            a[mt][2] = *(uint32_t*)&sA[(base + gid)     * PADH + k0 + tig * 2 + 8];
            a[mt][3] = *(uint32_t*)&sA[(base + gid + 8) * PADH + k0 + tig * 2 + 8];
        }
#pragma unroll
        for (int j = 0; j < 8; j++) {
            int col = wc * 64 + j * 8 + gid;
            uint32_t b0 = *(uint32_t*)&sWt[col * PADH + k0 + tig * 2];
            uint32_t b1 = *(uint32_t*)&sWt[col * PADH + k0 + tig * 2 + 8];
            mma_f16(acc[0][j], a[0], b0, b1);
            mma_f16(acc[1][j], a[1], b0, b1);
        }
    }
    __syncthreads();

#pragma unroll
    for (int mt = 0; mt < 2; mt++) {
        int lr0 = wr * 32 + mt * 16 + gid;
        int lr1 = lr0 + 8;
        int r0 = row0 + lr0, r1 = row0 + lr1;
        int gg0 = 0, gg1 = 0;
        if (FINAL == 1) {
            gg0 = (r0 < n) ? batch[r0] : 0;
            gg1 = (r1 < n) ? batch[r1] : 0;
        }
        float ps0 = 0.f, pd0 = 0.f, ps1 = 0.f, pd1 = 0.f;
#pragma unroll
        for (int j = 0; j < 8; j++) {
            int col = wc * 64 + j * 8 + tig * 2;
            float bb0 = __ldg(&bias[col]), bb1 = __ldg(&bias[col + 1]);
            float v00 = fmaxf(acc[mt][j][0] + bb0, 0.f);
            float v01 = fmaxf(acc[mt][j][1] + bb1, 0.f);
            float v10 = fmaxf(acc[mt][j][2] + bb0, 0.f);
            float v11 = fmaxf(acc[mt][j][3] + bb1, 0.f);
            if (FINAL == 0) {
                float av0 = __ldg(&csv[col]), av1 = __ldg(&csv[col + 1]);
                float dv0 = __ldg(&cdv[col]), dv1 = __ldg(&cdv[col + 1]);
                if (r0 < n)
                    *(__half2*)&g_xph[(size_t)r0 * 128 + col] = __floats2half2_rn(v00, v01);
                if (r1 < n)
                    *(__half2*)&g_xph[(size_t)r1 * 128 + col] = __floats2half2_rn(v10, v11);
                ps0 += v00 * av0 + v01 * av1;
                pd0 += v00 * dv0 + v01 * dv1;
                ps1 += v10 * av0 + v11 * av1;
                pd1 += v10 * dv0 + v11 * dv1;
            } else {
                float n00 = __shfl_xor_sync(FULLMASK, v00, 1);
                float n01 = __shfl_xor_sync(FULLMASK, v01, 1);
                float n10 = __shfl_xor_sync(FULLMASK, v10, 1);
                float n11 = __shfl_xor_sync(FULLMASK, v11, 1);
                if ((tig & 1) == 0) {
                    int cb = wc * 64 + j * 8 + tig * 2;
                    if (r0 < n)
                        atomicAdd((float4*)&g_pool[gg0 * 128 + cb],
                                  make_float4(v00, v01, n00, n01));
                    if (r1 < n)
                        atomicAdd((float4*)&g_pool[gg1 * 128 + cb],
                                  make_float4(v10, v11, n10, n11));
                }
            }
        }
        if (FINAL == 0) {
            atomicAdd(&sS[lr0], ps0); atomicAdd(&sD[lr0], pd0);
            atomicAdd(&sS[lr1], ps1); atomicAdd(&sD[lr1], pd1);
        } else if (wc == 0 && tig == 0) {
            if (r0 < n) atomicAdd(&g_pool[NG * HID + gg0], 1.0f);
            if (r1 < n) atomicAdd(&g_pool[NG * HID + gg1], 1.0f);
        }
    }
    if (FINAL == 0) {
        __syncthreads();
        if (tid < 128 && row0 + tid < n) {
            g_als[row0 + tid] = sS[tid];
            g_ald[row0 + tid] = sD[tid];
        }
    }
}

// ================= head (re-zeroes g_pool for next replay) =================
__global__ void k_final(const float* __restrict__ Wlin, const float* __restrict__ blin,
                        float* __restrict__ out) {
    int g = blockIdx.x;
    int j = threadIdx.x;
    __shared__ float s0[128], s1[128];
    float w0 = Wlin[j * 2 + 0];   // input-only prologue
    float w1 = Wlin[j * 2 + 1];
    pdl_wait();                   // g_pool written by gemm3
    float cnt = fmaxf(g_pool[NG * HID + g], 1.0f);
    float p = g_pool[g * 128 + j] / cnt;
    s0[j] = p * w0;
    s1[j] = p * w1;
    __syncthreads();
    g_pool[g * 128 + j] = 0.f;
    if (j == 0) g_pool[NG * HID + g] = 0.f;
#pragma unroll
    for (int st = 64; st > 0; st >>= 1) {
        if (j < st) { s0[j] += s0[j + st]; s1[j] += s1[j + st]; }
        __syncthreads();
    }
    if (j == 0) {
        out[g * 2 + 0] = 1.0f / (1.0f + __expf(-(s0[0] + blin[0])));
        out[g * 2 + 1] = 1.0f / (1.0f + __expf(-(s1[0] + blin[1])));
    }
}

// ================= host =================
extern "C" void kernel_launch(void* const* d_in, const int* in_sizes, int n_in,
                              void* d_out, int out_size) {
    const float* x     = (const float*)d_in[0];
    const int*   ei    = (const int*)d_in[1];
    const int*   batch = (const int*)d_in[2];
    const float* Wl[3] = { (const float*)d_in[3], (const float*)d_in[7],  (const float*)d_in[11] };
    const float* As[3] = { (const float*)d_in[4], (const float*)d_in[8],  (const float*)d_in[12] };
    const float* Ad[3] = { (const float*)d_in[5], (const float*)d_in[9],  (const float*)d_in[13] };
    const float* Bs[3] = { (const float*)d_in[6], (const float*)d_in[10], (const float*)d_in[14] };
    const float* Wlin  = (const float*)d_in[15];
    const float* blin  = (const float*)d_in[16];
    float* out = (float*)d_out;

    int n = in_sizes[0];
    int E = in_sizes[1] / 2;
    if (n > NMAX) n = NMAX;
    if (E > EMAX) E = EMAX;

    const int TB = 256;
    dim3 gE((E + TB - 1) / TB);
    dim3 gNW(((size_t)n * 32 + TB - 1) / TB);
    dim3 gG((n + 127) / 128);
    int nBlk = (n + 1023) / 1024;

    static cudaStream_t s2 = nullptr;
    static cudaEvent_t evFork = nullptr, evJoin = nullptr;
    if (!s2) {
        cudaStreamCreateWithFlags(&s2, cudaStreamNonBlocking);
        cudaEventCreateWithFlags(&evFork, cudaEventDisableTiming);
        cudaEventCreateWithFlags(&evJoin, cudaEventDisableTiming);
        cudaFuncSetAttribute(k_gemm_tc<0>, cudaFuncAttributeMaxDynamicSharedMemorySize, GEMM_SMEM);
        cudaFuncSetAttribute(k_gemm_tc<1>, cudaFuncAttributeMaxDynamicSharedMemorySize, GEMM_SMEM);
    }

    cudaLaunchAttribute pdlAttr[1];
    pdlAttr[0].id = cudaLaunchAttributeProgrammaticStreamSerialization;
    pdlAttr[0].val.programmaticStreamSerializationAllowed = 1;

    // fork: CSR build on s2 (PDL-chained); prep on main
    cudaEventRecord(evFork, 0);
    cudaStreamWaitEvent(s2, evFork, 0);

    k_hist<<<gE, TB, 0, s2>>>(ei, E);
    {
        cudaLaunchConfig_t cfg = {};
        cfg.gridDim = dim3(nBlk); cfg.blockDim = dim3(1024);
        cfg.stream = s2;
        cfg.attrs = pdlAttr; cfg.numAttrs = 1;
        cudaLaunchKernelEx(&cfg, k_scan_blk, n);
    }
    {
        cudaLaunchConfig_t cfg = {};
        cfg.gridDim = dim3(nBlk); cfg.blockDim = dim3(1024);
        cfg.stream = s2;
        cfg.attrs = pdlAttr; cfg.numAttrs = 1;
        cudaLaunchKernelEx(&cfg, k_scan_add, n, nBlk);
    }
    {
        cudaLaunchConfig_t cfg = {};
        cfg.gridDim = gE; cfg.blockDim = dim3(TB);
        cfg.stream = s2;
        cfg.attrs = pdlAttr; cfg.numAttrs = 1;
        cudaLaunchKernelEx(&cfg, k_scatter, ei, E);
    }
    cudaEventRecord(evJoin, s2);

    k_prep<<<32, 256>>>(Wl[1], As[1], Ad[1], Wl[2], As[2], Ad[2]);

    cudaStreamWaitEvent(0, evJoin, 0);

    // layer 1: scalar agg + expand
    k_l1agg<<<gNW, TB>>>(x, Wl[0], As[0], Ad[0], Bs[0], n);

    // layer 2: wide agg -> fp16 GEMM (PDL chain)
    {
        cudaLaunchConfig_t cfg = {};
        cfg.gridDim = gNW; cfg.blockDim = dim3(TB);
        cfg.attrs = pdlAttr; cfg.numAttrs = 1;
        cudaLaunchKernelEx(&cfg, k_gat_agg, n);
    }
    {
        cudaLaunchConfig_t cfg = {};
        cfg.gridDim = gG; cfg.blockDim = dim3(TB);
        cfg.dynamicSmemBytes = GEMM_SMEM;
        cfg.attrs = pdlAttr; cfg.numAttrs = 1;
        cudaLaunchKernelEx(&cfg, k_gemm_tc<0>, Wl[1], Bs[1],
                           (const float*)(g_cs + 256), (const float*)(g_cs + 384), batch, n);
    }
    // layer 3: wide agg -> fp16 GEMM (pools directly)
    {
        cudaLaunchConfig_t cfg = {};
        cfg.gridDim = gNW; cfg.blockDim = dim3(TB);
        cfg.attrs = pdlAttr; cfg.numAttrs = 1;
        cudaLaunchKernelEx(&cfg, k_gat_agg, n);
    }
    {
        cudaLaunchConfig_t cfg = {};
        cfg.gridDim = gG; cfg.blockDim = dim3(TB);
        cfg.dynamicSmemBytes = GEMM_SMEM;
        cfg.attrs = pdlAttr; cfg.numAttrs = 1;
        cudaLaunchKernelEx(&cfg, k_gemm_tc<1>, Wl[2], Bs[2],
                           (const float*)nullptr, (const float*)nullptr, batch, n);
    }
    {
        cudaLaunchConfig_t cfg = {};
        cfg.gridDim = dim3(NG); cfg.blockDim = dim3(128);
        cfg.attrs = pdlAttr; cfg.numAttrs = 1;
        cudaLaunchKernelEx(&cfg, k_final, Wlin, blin, out);
    }
}